// round 6
// baseline (speedup 1.0000x reference)
#include <cuda_runtime.h>
#include <cuda_bf16.h>
#include <cstdint>

#define S_LEN 8192
#define FD 128
#define TI 4
#define NT 256
#define STB 272   // bytes per smem row (136 bf16); LDSM conflict-free

// ---- smem layout (byte offsets), each buffer 128*272 = 34816 B ----
#define A_HI  0u
#define A_LO  34816u
#define B1_HI 69632u
#define B1_LO 104448u
#define B2_HI 139264u
#define B2_LO 174080u
#define SMEM_BYTES 208896

// ---------------- helpers ----------------
__device__ __forceinline__ uint32_t smem_u32(const void* p) {
    return (uint32_t)__cvta_generic_to_shared(p);
}
__device__ __forceinline__ void sts_pair(char* sm, uint32_t off, int row, int col, uint32_t v) {
    *(uint32_t*)(sm + off + row * STB + col * 2) = v;
}
__device__ __forceinline__ void split2(float a, float b, uint32_t& hi, uint32_t& lo) {
    __nv_bfloat16 ha = __float2bfloat16(a), hb = __float2bfloat16(b);
    __nv_bfloat162 H; H.x = ha; H.y = hb;
    hi = *reinterpret_cast<uint32_t*>(&H);
    __nv_bfloat162 L = __floats2bfloat162_rn(a - __bfloat162float(ha), b - __bfloat162float(hb));
    lo = *reinterpret_cast<uint32_t*>(&L);
}
__device__ __forceinline__ void mma16816(float* d, const uint32_t* a, uint32_t b0, uint32_t b1) {
    asm volatile(
        "mma.sync.aligned.m16n8k16.row.col.f32.bf16.bf16.f32 "
        "{%0,%1,%2,%3}, {%4,%5,%6,%7}, {%8,%9}, {%0,%1,%2,%3};"
        : "+f"(d[0]), "+f"(d[1]), "+f"(d[2]), "+f"(d[3])
        : "r"(a[0]), "r"(a[1]), "r"(a[2]), "r"(a[3]), "r"(b0), "r"(b1));
}
__device__ __forceinline__ void ldsm4(uint32_t* r, uint32_t a) {
    asm volatile("ldmatrix.sync.aligned.m8n8.x4.shared.b16 {%0,%1,%2,%3}, [%4];"
                 : "=r"(r[0]), "=r"(r[1]), "=r"(r[2]), "=r"(r[3]) : "r"(a));
}
__device__ __forceinline__ void ldsm4t(uint32_t* r, uint32_t a) {
    asm volatile("ldmatrix.sync.aligned.m8n8.x4.trans.shared.b16 {%0,%1,%2,%3}, [%4];"
                 : "=r"(r[0]), "=r"(r[1]), "=r"(r[2]), "=r"(r[3]) : "r"(a));
}
__device__ __forceinline__ void cpa16(uint32_t dst, const void* src) {
    asm volatile("cp.async.ca.shared.global [%0], [%1], 16;" :: "r"(dst), "l"(src));
}
#define CPA_COMMIT() asm volatile("cp.async.commit_group;" ::: "memory")
#define CPA_WAIT()   asm volatile("cp.async.wait_group 0;" ::: "memory")

// ---------------- precomputed operand images (bf16 hi/lo, stride-136) ----------------
__device__ __align__(16) __nv_bfloat16 g_Mt_hi[128 * 136];
__device__ __align__(16) __nv_bfloat16 g_Mt_lo[128 * 136];
__device__ __align__(16) __nv_bfloat16 g_Wv_hi[128 * 136];
__device__ __align__(16) __nv_bfloat16 g_Wv_lo[128 * 136];

__global__ void prep_kernel(const float* __restrict__ Wq, const float* __restrict__ Wk,
                            const float* __restrict__ Wv) {
    int n = blockIdx.x, k = threadIdx.x;
    float acc = 0.f;
#pragma unroll 8
    for (int l = 0; l < FD; ++l)
        acc += Wq[l * FD + k] * Wk[l * FD + n];
    acc *= 0.08838834764831845f;  // 1/sqrt(128)
    int idx = n * 136 + k;
    __nv_bfloat16 h = __float2bfloat16(acc);
    g_Mt_hi[idx] = h;
    g_Mt_lo[idx] = __float2bfloat16(acc - __bfloat162float(h));
    float wv = Wv[n * FD + k];
    h = __float2bfloat16(wv);
    g_Wv_hi[idx] = h;
    g_Wv_lo[idx] = __float2bfloat16(wv - __bfloat162float(h));
}

// load a 128x128 fp32 tile (row r = it*32+b), split, store hi/lo stride-136
__device__ __forceinline__ void load_split(const float* __restrict__ base, uint32_t i0,
                                           char* sm, uint32_t dHi, uint32_t dLo, int t) {
    int r = t >> 1;
    int h4 = (t & 1) * 4;
    const float* row = base + ((size_t)(r & 31) * S_LEN + (i0 + (r >> 5))) * FD;
#pragma unroll
    for (int u = 0; u < 16; ++u) {
        int col = 8 * u + h4;
        float4 x = *(const float4*)(row + col);
        uint32_t h0, l0, h1, l1;
        split2(x.x, x.y, h0, l0);
        split2(x.z, x.w, h1, l1);
        sts_pair(sm, dHi, r, col, h0);
        sts_pair(sm, dHi, r, col + 2, h1);
        sts_pair(sm, dLo, r, col, l0);
        sts_pair(sm, dLo, r, col + 2, l1);
    }
}

// full 128x128x128 bf16x3 GEMM, warp tile 32m x 64n, LDSM operand fetch
__device__ __forceinline__ void gemm_full(uint32_t sbase, float acc[2][8][4],
                                          int mBase, int nBase,
                                          uint32_t aLane, uint32_t bLane,
                                          uint32_t aH, uint32_t aL,
                                          uint32_t bH, uint32_t bL) {
#pragma unroll 1
    for (int pass = 0; pass < 3; ++pass) {
        uint32_t aOff = sbase + ((pass == 2) ? aL : aH) + aLane + mBase * STB;
        uint32_t bOff = sbase + ((pass == 1) ? bL : bH) + bLane + nBase * STB;
#pragma unroll
        for (int ks = 0; ks < 8; ++ks) {
            uint32_t kb = ks * 32;
            uint32_t a[2][4];
            ldsm4(a[0], aOff + kb);
            ldsm4(a[1], aOff + 16 * STB + kb);
#pragma unroll
            for (int p = 0; p < 4; ++p) {
                uint32_t b[4];
                ldsm4(b, bOff + p * 16 * STB + kb);
                mma16816(acc[0][2 * p],     a[0], b[0], b[1]);
                mma16816(acc[0][2 * p + 1], a[0], b[2], b[3]);
                mma16816(acc[1][2 * p],     a[1], b[0], b[1]);
                mma16816(acc[1][2 * p + 1], a[1], b[2], b[3]);
            }
        }
    }
}

__global__ __launch_bounds__(NT, 1)
void fused_attn_mma(const float* __restrict__ Q, const float* __restrict__ K,
                    const float* __restrict__ V, float* __restrict__ Out) {
    extern __shared__ char sm[];
    const uint32_t sbase = smem_u32(sm);
    const int t = threadIdx.x, lane = t & 31, w = t >> 5;
    const int g = lane >> 2, tg = lane & 3;
    const uint32_t i0 = blockIdx.x * TI;

    // LDSM per-lane address components
    const uint32_t aLane = (uint32_t)(lane & 15) * STB + (uint32_t)(lane >> 4) * 16;
    const uint32_t bLane = (uint32_t)((lane & 7) + ((lane & 16) >> 1)) * STB + (uint32_t)(lane & 8) * 2;
    const uint32_t tLane = (uint32_t)((lane & 7) + (lane & 8)) * STB + (uint32_t)(lane >> 4) * 16;

    // ---- P0: Mt -> B1 (cp.async), Q -> A, K -> B2 ----
    {
        const char* mh = (const char*)g_Mt_hi;
        const char* ml = (const char*)g_Mt_lo;
#pragma unroll
        for (int u = 0; u < 9; ++u) {
            int i = u * NT + t;
            if (i < 2176) {
                cpa16(sbase + B1_HI + i * 16, mh + i * 16);
                cpa16(sbase + B1_LO + i * 16, ml + i * 16);
            }
        }
        CPA_COMMIT();
    }
    load_split(Q, i0, sm, A_HI, A_LO, t);
    load_split(K, i0, sm, B2_HI, B2_LO, t);
    CPA_WAIT();
    __syncthreads();

    // ---- G1: QM = Q @ Mt^T ----
    const int mB = (w >> 1) * 32, nB = (w & 1) * 64;
    float acc[2][8][4];
#pragma unroll
    for (int mt = 0; mt < 2; ++mt)
#pragma unroll
        for (int nt = 0; nt < 8; ++nt)
#pragma unroll
            for (int j = 0; j < 4; ++j) acc[mt][nt][j] = 0.f;
    gemm_full(sbase, acc, mB, nB, aLane, bLane, A_HI, A_LO, B1_HI, B1_LO);
    __syncthreads();

    // ---- P1: QM frags -> A (hi/lo); V (natural layout) -> B1 ----
#pragma unroll
    for (int mt = 0; mt < 2; ++mt)
#pragma unroll
        for (int nt = 0; nt < 8; ++nt) {
            int r = mB + mt * 16 + g, c = nB + nt * 8 + tg * 2;
            uint32_t h, l;
            split2(acc[mt][nt][0], acc[mt][nt][1], h, l);
            sts_pair(sm, A_HI, r, c, h);
            sts_pair(sm, A_LO, r, c, l);
            split2(acc[mt][nt][2], acc[mt][nt][3], h, l);
            sts_pair(sm, A_HI, r + 8, c, h);
            sts_pair(sm, A_LO, r + 8, c, l);
        }
    load_split(V, i0, sm, B1_HI, B1_LO, t);
    __syncthreads();

    // ---- G2: diagonal scores (warp strip: 16 rows x 32 cols) ----
    const int it = w >> 1;
    const int mB2 = it * 32 + (w & 1) * 16;
    const int nB2 = it * 32;
    float sc[4][4];
#pragma unroll
    for (int nt = 0; nt < 4; ++nt)
#pragma unroll
        for (int j = 0; j < 4; ++j) sc[nt][j] = 0.f;
#pragma unroll 1
    for (int pass = 0; pass < 3; ++pass) {
        uint32_t aOff = sbase + ((pass == 2) ? A_LO : A_HI) + aLane + mB2 * STB;
        uint32_t bOff = sbase + ((pass == 1) ? B2_LO : B2_HI) + bLane + nB2 * STB;
#pragma unroll
        for (int ks = 0; ks < 8; ++ks) {
            uint32_t kb = ks * 32;
            uint32_t a[4];
            ldsm4(a, aOff + kb);
            uint32_t b0[4], b1[4];
            ldsm4(b0, bOff + kb);
            ldsm4(b1, bOff + 16 * STB + kb);
            mma16816(sc[0], a, b0[0], b0[1]);
            mma16816(sc[1], a, b0[2], b0[3]);
            mma16816(sc[2], a, b1[0], b1[1]);
            mma16816(sc[3], a, b1[2], b1[3]);
        }
    }

    // ---- softmax over 32 cols (rows g and g+8 of this warp strip) ----
    {
        float mx0 = -1e30f, mx1 = -1e30f;
#pragma unroll
        for (int nt = 0; nt < 4; ++nt) {
            mx0 = fmaxf(mx0, fmaxf(sc[nt][0], sc[nt][1]));
            mx1 = fmaxf(mx1, fmaxf(sc[nt][2], sc[nt][3]));
        }
        mx0 = fmaxf(mx0, __shfl_xor_sync(0xffffffffu, mx0, 1));
        mx0 = fmaxf(mx0, __shfl_xor_sync(0xffffffffu, mx0, 2));
        mx1 = fmaxf(mx1, __shfl_xor_sync(0xffffffffu, mx1, 1));
        mx1 = fmaxf(mx1, __shfl_xor_sync(0xffffffffu, mx1, 2));
        float s0 = 0.f, s1 = 0.f;
#pragma unroll
        for (int nt = 0; nt < 4; ++nt) {
            sc[nt][0] = __expf(sc[nt][0] - mx0);
            sc[nt][1] = __expf(sc[nt][1] - mx0);
            sc[nt][2] = __expf(sc[nt][2] - mx1);
            sc[nt][3] = __expf(sc[nt][3] - mx1);
            s0 += sc[nt][0] + sc[nt][1];
            s1 += sc[nt][2] + sc[nt][3];
        }
        s0 += __shfl_xor_sync(0xffffffffu, s0, 1);
        s0 += __shfl_xor_sync(0xffffffffu, s0, 2);
        s1 += __shfl_xor_sync(0xffffffffu, s1, 1);
        s1 += __shfl_xor_sync(0xffffffffu, s1, 2);
        float i0v = 1.f / s0, i1v = 1.f / s1;
#pragma unroll
        for (int nt = 0; nt < 4; ++nt) {
            sc[nt][0] *= i0v; sc[nt][1] *= i0v;
            sc[nt][2] *= i1v; sc[nt][3] *= i1v;
        }
    }
    // attn A-fragments (hi/lo) directly from D-fragments (layouts coincide)
    uint32_t a3H[2][4], a3L[2][4];
#pragma unroll
    for (int ks = 0; ks < 2; ++ks) {
        int n0 = ks * 2, n1 = ks * 2 + 1;
        split2(sc[n0][0], sc[n0][1], a3H[ks][0], a3L[ks][0]);
        split2(sc[n0][2], sc[n0][3], a3H[ks][1], a3L[ks][1]);
        split2(sc[n1][0], sc[n1][1], a3H[ks][2], a3L[ks][2]);
        split2(sc[n1][2], sc[n1][3], a3H[ks][3], a3L[ks][3]);
    }
    __syncthreads();   // everyone done reading A (QM) and B2 (K)

    // ---- Wv -> B2 via cp.async, overlapped with G3 ----
    {
        const char* wh = (const char*)g_Wv_hi;
        const char* wl = (const char*)g_Wv_lo;
#pragma unroll
        for (int u = 0; u < 9; ++u) {
            int i = u * NT + t;
            if (i < 2176) {
                cpa16(sbase + B2_HI + i * 16, wh + i * 16);
                cpa16(sbase + B2_LO + i * 16, wl + i * 16);
            }
        }
        CPA_COMMIT();
    }

    // ---- G3: raw = attn(block-diag) @ V   (B via ldmatrix.trans on natural V) ----
    float acc3[16][4];
#pragma unroll
    for (int nt = 0; nt < 16; ++nt)
#pragma unroll
        for (int j = 0; j < 4; ++j) acc3[nt][j] = 0.f;
#pragma unroll 1
    for (int pass = 0; pass < 3; ++pass) {
        uint32_t bOff = sbase + ((pass == 1) ? B1_LO : B1_HI) + tLane + (uint32_t)(it * 32) * STB;
#pragma unroll
        for (int ks = 0; ks < 2; ++ks) {
            const uint32_t* av = (pass == 2) ? a3L[ks] : a3H[ks];
#pragma unroll
            for (int p = 0; p < 8; ++p) {
                uint32_t b[4];
                ldsm4t(b, bOff + (uint32_t)(ks * 16) * STB + p * 32);
                mma16816(acc3[2 * p],     av, b[0], b[1]);
                mma16816(acc3[2 * p + 1], av, b[2], b[3]);
            }
        }
    }

    // ---- raw frags -> A (hi/lo) ----
    {
        int r0 = it * 32 + (w & 1) * 16 + g;
#pragma unroll
        for (int nt = 0; nt < 16; ++nt) {
            int c = nt * 8 + tg * 2;
            uint32_t h, l;
            split2(acc3[nt][0], acc3[nt][1], h, l);
            sts_pair(sm, A_HI, r0, c, h);
            sts_pair(sm, A_LO, r0, c, l);
            split2(acc3[nt][2], acc3[nt][3], h, l);
            sts_pair(sm, A_HI, r0 + 8, c, h);
            sts_pair(sm, A_LO, r0 + 8, c, l);
        }
    }
    CPA_WAIT();
    __syncthreads();

    // ---- G4: Out = raw @ Wv^T ----
    float acc4[2][8][4];
#pragma unroll
    for (int mt = 0; mt < 2; ++mt)
#pragma unroll
        for (int nt = 0; nt < 8; ++nt)
#pragma unroll
            for (int j = 0; j < 4; ++j) acc4[mt][nt][j] = 0.f;
    gemm_full(sbase, acc4, mB, nB, aLane, bLane, A_HI, A_LO, B2_HI, B2_LO);

    // ---- store ----
#pragma unroll
    for (int mt = 0; mt < 2; ++mt) {
        int r = mB + mt * 16 + g;
#pragma unroll
        for (int nt = 0; nt < 8; ++nt) {
            int c = nB + nt * 8 + tg * 2;
            {
                int b = r & 31, itt = r >> 5;
                float2 v = {acc4[mt][nt][0], acc4[mt][nt][1]};
                *(float2*)(Out + ((size_t)b * S_LEN + (i0 + itt)) * FD + c) = v;
            }
            {
                int r8 = r + 8;
                int b = r8 & 31, itt = r8 >> 5;
                float2 v = {acc4[mt][nt][2], acc4[mt][nt][3]};
                *(float2*)(Out + ((size_t)b * S_LEN + (i0 + itt)) * FD + c) = v;
            }
        }
    }
}

extern "C" void kernel_launch(void* const* d_in, const int* in_sizes, int n_in,
                              void* d_out, int out_size) {
    const float* q  = (const float*)d_in[0];
    const float* k  = (const float*)d_in[1];
    const float* v  = (const float*)d_in[2];
    const float* Wq = (const float*)d_in[3];
    const float* Wk = (const float*)d_in[4];
    const float* Wv = (const float*)d_in[5];
    float* out = (float*)d_out;

    prep_kernel<<<FD, FD>>>(Wq, Wk, Wv);

    cudaFuncSetAttribute(fused_attn_mma,
                         cudaFuncAttributeMaxDynamicSharedMemorySize, SMEM_BYTES);
    fused_attn_mma<<<S_LEN / TI, NT, SMEM_BYTES>>>(q, k, v, out);
}

// round 7
// speedup vs baseline: 1.0022x; 1.0022x over previous
#include <cuda_runtime.h>
#include <cuda_bf16.h>
#include <cstdint>

#define S_LEN 8192
#define FD 128
#define TI 4
#define NT 256
#define STB 272   // bytes per smem row (136 bf16); LDSM conflict-free

// ---- smem layout (byte offsets), each buffer 128*272 = 34816 B ----
#define A_HI  0u
#define A_LO  34816u
#define B1_HI 69632u
#define B1_LO 104448u
#define B2_HI 139264u
#define B2_LO 174080u
#define SMEM_BYTES 208896

// ---------------- helpers ----------------
__device__ __forceinline__ uint32_t smem_u32(const void* p) {
    return (uint32_t)__cvta_generic_to_shared(p);
}
__device__ __forceinline__ void sts_pair(char* sm, uint32_t off, int row, int col, uint32_t v) {
    *(uint32_t*)(sm + off + row * STB + col * 2) = v;
}
__device__ __forceinline__ void split2(float a, float b, uint32_t& hi, uint32_t& lo) {
    __nv_bfloat16 ha = __float2bfloat16(a), hb = __float2bfloat16(b);
    __nv_bfloat162 H; H.x = ha; H.y = hb;
    hi = *reinterpret_cast<uint32_t*>(&H);
    __nv_bfloat162 L = __floats2bfloat162_rn(a - __bfloat162float(ha), b - __bfloat162float(hb));
    lo = *reinterpret_cast<uint32_t*>(&L);
}
__device__ __forceinline__ void mma16816(float* d, const uint32_t* a, uint32_t b0, uint32_t b1) {
    asm volatile(
        "mma.sync.aligned.m16n8k16.row.col.f32.bf16.bf16.f32 "
        "{%0,%1,%2,%3}, {%4,%5,%6,%7}, {%8,%9}, {%0,%1,%2,%3};"
        : "+f"(d[0]), "+f"(d[1]), "+f"(d[2]), "+f"(d[3])
        : "r"(a[0]), "r"(a[1]), "r"(a[2]), "r"(a[3]), "r"(b0), "r"(b1));
}
__device__ __forceinline__ void ldsm4(uint32_t* r, uint32_t a) {
    asm volatile("ldmatrix.sync.aligned.m8n8.x4.shared.b16 {%0,%1,%2,%3}, [%4];"
                 : "=r"(r[0]), "=r"(r[1]), "=r"(r[2]), "=r"(r[3]) : "r"(a));
}
__device__ __forceinline__ void ldsm4t(uint32_t* r, uint32_t a) {
    asm volatile("ldmatrix.sync.aligned.m8n8.x4.trans.shared.b16 {%0,%1,%2,%3}, [%4];"
                 : "=r"(r[0]), "=r"(r[1]), "=r"(r[2]), "=r"(r[3]) : "r"(a));
}
__device__ __forceinline__ void cpa16(uint32_t dst, const void* src) {
    asm volatile("cp.async.ca.shared.global [%0], [%1], 16;" :: "r"(dst), "l"(src));
}
#define CPA_COMMIT() asm volatile("cp.async.commit_group;" ::: "memory")
#define CPA_WAIT()   asm volatile("cp.async.wait_group 0;" ::: "memory")

// ---------------- precomputed operand images (bf16 hi/lo, stride-136) ----------------
__device__ __align__(16) __nv_bfloat16 g_Mt_hi[128 * 136];
__device__ __align__(16) __nv_bfloat16 g_Mt_lo[128 * 136];
__device__ __align__(16) __nv_bfloat16 g_Wv_hi[128 * 136];
__device__ __align__(16) __nv_bfloat16 g_Wv_lo[128 * 136];

__global__ void prep_kernel(const float* __restrict__ Wq, const float* __restrict__ Wk,
                            const float* __restrict__ Wv) {
    int n = blockIdx.x, k = threadIdx.x;
    float acc = 0.f;
#pragma unroll 8
    for (int l = 0; l < FD; ++l)
        acc += Wq[l * FD + k] * Wk[l * FD + n];
    acc *= 0.08838834764831845f;  // 1/sqrt(128)
    int idx = n * 136 + k;
    __nv_bfloat16 h = __float2bfloat16(acc);
    g_Mt_hi[idx] = h;
    g_Mt_lo[idx] = __float2bfloat16(acc - __bfloat162float(h));
    float wv = Wv[n * FD + k];
    h = __float2bfloat16(wv);
    g_Wv_hi[idx] = h;
    g_Wv_lo[idx] = __float2bfloat16(wv - __bfloat162float(h));
}

// load a 128x128 fp32 tile (row r = it*32+b), split, store hi/lo stride-136
__device__ __forceinline__ void load_split(const float* __restrict__ base, uint32_t i0,
                                           char* sm, uint32_t dHi, uint32_t dLo, int t) {
    int r = t >> 1;
    int h4 = (t & 1) * 4;
    const float* row = base + ((size_t)(r & 31) * S_LEN + (i0 + (r >> 5))) * FD;
#pragma unroll
    for (int u = 0; u < 16; ++u) {
        int col = 8 * u + h4;
        float4 x = *(const float4*)(row + col);
        uint32_t h0, l0, h1, l1;
        split2(x.x, x.y, h0, l0);
        split2(x.z, x.w, h1, l1);
        sts_pair(sm, dHi, r, col, h0);
        sts_pair(sm, dHi, r, col + 2, h1);
        sts_pair(sm, dLo, r, col, l0);
        sts_pair(sm, dLo, r, col + 2, l1);
    }
}

// full 128x128x128 bf16x3 GEMM, warp tile 32m x 64n, LDSM operand fetch
__device__ __forceinline__ void gemm_full(uint32_t sbase, float acc[2][8][4],
                                          int mBase, int nBase,
                                          uint32_t aLane, uint32_t bLane,
                                          uint32_t aH, uint32_t aL,
                                          uint32_t bH, uint32_t bL) {
#pragma unroll 1
    for (int pass = 0; pass < 3; ++pass) {
        uint32_t aOff = sbase + ((pass == 2) ? aL : aH) + aLane + mBase * STB;
        uint32_t bOff = sbase + ((pass == 1) ? bL : bH) + bLane + nBase * STB;
#pragma unroll
        for (int ks = 0; ks < 8; ++ks) {
            uint32_t kb = ks * 32;
            uint32_t a[2][4];
            ldsm4(a[0], aOff + kb);
            ldsm4(a[1], aOff + 16 * STB + kb);
#pragma unroll
            for (int p = 0; p < 4; ++p) {
                uint32_t b[4];
                ldsm4(b, bOff + p * 16 * STB + kb);
                mma16816(acc[0][2 * p],     a[0], b[0], b[1]);
                mma16816(acc[0][2 * p + 1], a[0], b[2], b[3]);
                mma16816(acc[1][2 * p],     a[1], b[0], b[1]);
                mma16816(acc[1][2 * p + 1], a[1], b[2], b[3]);
            }
        }
    }
}

__global__ __launch_bounds__(NT, 1)
void fused_attn_mma(const float* __restrict__ Q, const float* __restrict__ K,
                    const float* __restrict__ V, float* __restrict__ Out) {
    extern __shared__ char sm[];
    const uint32_t sbase = smem_u32(sm);
    const int t = threadIdx.x, lane = t & 31, w = t >> 5;
    const int g = lane >> 2, tg = lane & 3;
    const uint32_t i0 = blockIdx.x * TI;

    // LDSM per-lane address components
    const uint32_t aLane = (uint32_t)(lane & 15) * STB + (uint32_t)(lane >> 4) * 16;
    const uint32_t bLane = (uint32_t)((lane & 7) + ((lane & 16) >> 1)) * STB + (uint32_t)(lane & 8) * 2;
    const uint32_t tLane = (uint32_t)((lane & 7) + (lane & 8)) * STB + (uint32_t)(lane >> 4) * 16;

    // ---- P0: Mt -> B1 (cp.async), Q -> A, K -> B2 ----
    {
        const char* mh = (const char*)g_Mt_hi;
        const char* ml = (const char*)g_Mt_lo;
#pragma unroll
        for (int u = 0; u < 9; ++u) {
            int i = u * NT + t;
            if (i < 2176) {
                cpa16(sbase + B1_HI + i * 16, mh + i * 16);
                cpa16(sbase + B1_LO + i * 16, ml + i * 16);
            }
        }
        CPA_COMMIT();
    }
    load_split(Q, i0, sm, A_HI, A_LO, t);
    load_split(K, i0, sm, B2_HI, B2_LO, t);
    CPA_WAIT();
    __syncthreads();

    // ---- G1: QM = Q @ Mt^T ----
    const int mB = (w >> 1) * 32, nB = (w & 1) * 64;
    float acc[2][8][4];
#pragma unroll
    for (int mt = 0; mt < 2; ++mt)
#pragma unroll
        for (int nt = 0; nt < 8; ++nt)
#pragma unroll
            for (int j = 0; j < 4; ++j) acc[mt][nt][j] = 0.f;
    gemm_full(sbase, acc, mB, nB, aLane, bLane, A_HI, A_LO, B1_HI, B1_LO);
    __syncthreads();

    // ---- P1: QM frags -> A (hi/lo); V (natural layout) -> B1 ----
#pragma unroll
    for (int mt = 0; mt < 2; ++mt)
#pragma unroll
        for (int nt = 0; nt < 8; ++nt) {
            int r = mB + mt * 16 + g, c = nB + nt * 8 + tg * 2;
            uint32_t h, l;
            split2(acc[mt][nt][0], acc[mt][nt][1], h, l);
            sts_pair(sm, A_HI, r, c, h);
            sts_pair(sm, A_LO, r, c, l);
            split2(acc[mt][nt][2], acc[mt][nt][3], h, l);
            sts_pair(sm, A_HI, r + 8, c, h);
            sts_pair(sm, A_LO, r + 8, c, l);
        }
    load_split(V, i0, sm, B1_HI, B1_LO, t);
    __syncthreads();

    // ---- G2: diagonal scores (warp strip: 16 rows x 32 cols) ----
    const int it = w >> 1;
    const int mB2 = it * 32 + (w & 1) * 16;
    const int nB2 = it * 32;
    float sc[4][4];
#pragma unroll
    for (int nt = 0; nt < 4; ++nt)
#pragma unroll
        for (int j = 0; j < 4; ++j) sc[nt][j] = 0.f;
#pragma unroll 1
    for (int pass = 0; pass < 3; ++pass) {
        uint32_t aOff = sbase + ((pass == 2) ? A_LO : A_HI) + aLane + mB2 * STB;
        uint32_t bOff = sbase + ((pass == 1) ? B2_LO : B2_HI) + bLane + nB2 * STB;
#pragma unroll
        for (int ks = 0; ks < 8; ++ks) {
            uint32_t kb = ks * 32;
            uint32_t a[4];
            ldsm4(a, aOff + kb);
            uint32_t b0[4], b1[4];
            ldsm4(b0, bOff + kb);
            ldsm4(b1, bOff + 16 * STB + kb);
            mma16816(sc[0], a, b0[0], b0[1]);
            mma16816(sc[1], a, b0[2], b0[3]);
            mma16816(sc[2], a, b1[0], b1[1]);
            mma16816(sc[3], a, b1[2], b1[3]);
        }
    }

    // ---- softmax over 32 cols (rows g and g+8 of this warp strip) ----
    {
        float mx0 = -1e30f, mx1 = -1e30f;
#pragma unroll
        for (int nt = 0; nt < 4; ++nt) {
            mx0 = fmaxf(mx0, fmaxf(sc[nt][0], sc[nt][1]));
            mx1 = fmaxf(mx1, fmaxf(sc[nt][2], sc[nt][3]));
        }
        mx0 = fmaxf(mx0, __shfl_xor_sync(0xffffffffu, mx0, 1));
        mx0 = fmaxf(mx0, __shfl_xor_sync(0xffffffffu, mx0, 2));
        mx1 = fmaxf(mx1, __shfl_xor_sync(0xffffffffu, mx1, 1));
        mx1 = fmaxf(mx1, __shfl_xor_sync(0xffffffffu, mx1, 2));
        float s0 = 0.f, s1 = 0.f;
#pragma unroll
        for (int nt = 0; nt < 4; ++nt) {
            sc[nt][0] = __expf(sc[nt][0] - mx0);
            sc[nt][1] = __expf(sc[nt][1] - mx0);
            sc[nt][2] = __expf(sc[nt][2] - mx1);
            sc[nt][3] = __expf(sc[nt][3] - mx1);
            s0 += sc[nt][0] + sc[nt][1];
            s1 += sc[nt][2] + sc[nt][3];
        }
        s0 += __shfl_xor_sync(0xffffffffu, s0, 1);
        s0 += __shfl_xor_sync(0xffffffffu, s0, 2);
        s1 += __shfl_xor_sync(0xffffffffu, s1, 1);
        s1 += __shfl_xor_sync(0xffffffffu, s1, 2);
        float i0v = 1.f / s0, i1v = 1.f / s1;
#pragma unroll
        for (int nt = 0; nt < 4; ++nt) {
            sc[nt][0] *= i0v; sc[nt][1] *= i0v;
            sc[nt][2] *= i1v; sc[nt][3] *= i1v;
        }
    }
    // attn A-fragments (hi/lo) directly from D-fragments (layouts coincide)
    uint32_t a3H[2][4], a3L[2][4];
#pragma unroll
    for (int ks = 0; ks < 2; ++ks) {
        int n0 = ks * 2, n1 = ks * 2 + 1;
        split2(sc[n0][0], sc[n0][1], a3H[ks][0], a3L[ks][0]);
        split2(sc[n0][2], sc[n0][3], a3H[ks][1], a3L[ks][1]);
        split2(sc[n1][0], sc[n1][1], a3H[ks][2], a3L[ks][2]);
        split2(sc[n1][2], sc[n1][3], a3H[ks][3], a3L[ks][3]);
    }
    __syncthreads();   // everyone done reading A (QM) and B2 (K)

    // ---- Wv -> B2 via cp.async, overlapped with G3 ----
    {
        const char* wh = (const char*)g_Wv_hi;
        const char* wl = (const char*)g_Wv_lo;
#pragma unroll
        for (int u = 0; u < 9; ++u) {
            int i = u * NT + t;
            if (i < 2176) {
                cpa16(sbase + B2_HI + i * 16, wh + i * 16);
                cpa16(sbase + B2_LO + i * 16, wl + i * 16);
            }
        }
        CPA_COMMIT();
    }

    // ---- G3: raw = attn(block-diag) @ V   (B via ldmatrix.trans on natural V) ----
    float acc3[16][4];
#pragma unroll
    for (int nt = 0; nt < 16; ++nt)
#pragma unroll
        for (int j = 0; j < 4; ++j) acc3[nt][j] = 0.f;
#pragma unroll 1
    for (int pass = 0; pass < 3; ++pass) {
        uint32_t bOff = sbase + ((pass == 1) ? B1_LO : B1_HI) + tLane + (uint32_t)(it * 32) * STB;
#pragma unroll
        for (int ks = 0; ks < 2; ++ks) {
            const uint32_t* av = (pass == 2) ? a3L[ks] : a3H[ks];
#pragma unroll
            for (int p = 0; p < 8; ++p) {
                uint32_t b[4];
                ldsm4t(b, bOff + (uint32_t)(ks * 16) * STB + p * 32);
                mma16816(acc3[2 * p],     av, b[0], b[1]);
                mma16816(acc3[2 * p + 1], av, b[2], b[3]);
            }
        }
    }

    // ---- raw frags -> A (hi/lo) ----
    {
        int r0 = it * 32 + (w & 1) * 16 + g;
#pragma unroll
        for (int nt = 0; nt < 16; ++nt) {
            int c = nt * 8 + tg * 2;
            uint32_t h, l;
            split2(acc3[nt][0], acc3[nt][1], h, l);
            sts_pair(sm, A_HI, r0, c, h);
            sts_pair(sm, A_LO, r0, c, l);
            split2(acc3[nt][2], acc3[nt][3], h, l);
            sts_pair(sm, A_HI, r0 + 8, c, h);
            sts_pair(sm, A_LO, r0 + 8, c, l);
        }
    }
    CPA_WAIT();
    __syncthreads();

    // ---- G4: Out = raw @ Wv^T ----
    float acc4[2][8][4];
#pragma unroll
    for (int mt = 0; mt < 2; ++mt)
#pragma unroll
        for (int nt = 0; nt < 8; ++nt)
#pragma unroll
            for (int j = 0; j < 4; ++j) acc4[mt][nt][j] = 0.f;
    gemm_full(sbase, acc4, mB, nB, aLane, bLane, A_HI, A_LO, B2_HI, B2_LO);

    // ---- store ----
#pragma unroll
    for (int mt = 0; mt < 2; ++mt) {
        int r = mB + mt * 16 + g;
#pragma unroll
        for (int nt = 0; nt < 8; ++nt) {
            int c = nB + nt * 8 + tg * 2;
            {
                int b = r & 31, itt = r >> 5;
                float2 v = {acc4[mt][nt][0], acc4[mt][nt][1]};
                *(float2*)(Out + ((size_t)b * S_LEN + (i0 + itt)) * FD + c) = v;
            }
            {
                int r8 = r + 8;
                int b = r8 & 31, itt = r8 >> 5;
                float2 v = {acc4[mt][nt][2], acc4[mt][nt][3]};
                *(float2*)(Out + ((size_t)b * S_LEN + (i0 + itt)) * FD + c) = v;
            }
        }
    }
}

extern "C" void kernel_launch(void* const* d_in, const int* in_sizes, int n_in,
                              void* d_out, int out_size) {
    const float* q  = (const float*)d_in[0];
    const float* k  = (const float*)d_in[1];
    const float* v  = (const float*)d_in[2];
    const float* Wq = (const float*)d_in[3];
    const float* Wk = (const float*)d_in[4];
    const float* Wv = (const float*)d_in[5];
    float* out = (float*)d_out;

    prep_kernel<<<FD, FD>>>(Wq, Wk, Wv);

    cudaFuncSetAttribute(fused_attn_mma,
                         cudaFuncAttributeMaxDynamicSharedMemorySize, SMEM_BYTES);
    fused_attn_mma<<<S_LEN / TI, NT, SMEM_BYTES>>>(q, k, v, out);
}

// round 8
// speedup vs baseline: 1.0497x; 1.0475x over previous
#include <cuda_runtime.h>
#include <cuda_bf16.h>
#include <cstdint>

#define S_LEN 8192
#define FD 128
#define TI 4
#define NT 256
#define STB 272   // bytes per smem row (136 bf16); LDSM conflict-free

// ---- smem layout (byte offsets), each buffer 128*272 = 34816 B ----
#define A_HI  0u
#define A_LO  34816u
#define B1_HI 69632u
#define B1_LO 104448u
#define B2_HI 139264u
#define B2_LO 174080u
#define SMEM_BYTES 208896

// ---------------- helpers ----------------
__device__ __forceinline__ uint32_t smem_u32(const void* p) {
    return (uint32_t)__cvta_generic_to_shared(p);
}
__device__ __forceinline__ void sts_pair(char* sm, uint32_t off, int row, int col, uint32_t v) {
    *(uint32_t*)(sm + off + row * STB + col * 2) = v;
}
__device__ __forceinline__ void split2(float a, float b, uint32_t& hi, uint32_t& lo) {
    __nv_bfloat16 ha = __float2bfloat16(a), hb = __float2bfloat16(b);
    __nv_bfloat162 H; H.x = ha; H.y = hb;
    hi = *reinterpret_cast<uint32_t*>(&H);
    __nv_bfloat162 L = __floats2bfloat162_rn(a - __bfloat162float(ha), b - __bfloat162float(hb));
    lo = *reinterpret_cast<uint32_t*>(&L);
}
__device__ __forceinline__ void mma16816(float* d, const uint32_t* a, uint32_t b0, uint32_t b1) {
    asm volatile(
        "mma.sync.aligned.m16n8k16.row.col.f32.bf16.bf16.f32 "
        "{%0,%1,%2,%3}, {%4,%5,%6,%7}, {%8,%9}, {%0,%1,%2,%3};"
        : "+f"(d[0]), "+f"(d[1]), "+f"(d[2]), "+f"(d[3])
        : "r"(a[0]), "r"(a[1]), "r"(a[2]), "r"(a[3]), "r"(b0), "r"(b1));
}
__device__ __forceinline__ void ldsm4(uint32_t* r, uint32_t a) {
    asm volatile("ldmatrix.sync.aligned.m8n8.x4.shared.b16 {%0,%1,%2,%3}, [%4];"
                 : "=r"(r[0]), "=r"(r[1]), "=r"(r[2]), "=r"(r[3]) : "r"(a));
}
__device__ __forceinline__ void ldsm4t(uint32_t* r, uint32_t a) {
    asm volatile("ldmatrix.sync.aligned.m8n8.x4.trans.shared.b16 {%0,%1,%2,%3}, [%4];"
                 : "=r"(r[0]), "=r"(r[1]), "=r"(r[2]), "=r"(r[3]) : "r"(a));
}
__device__ __forceinline__ void cpa16(uint32_t dst, const void* src) {
    asm volatile("cp.async.ca.shared.global [%0], [%1], 16;" :: "r"(dst), "l"(src));
}
#define CPA_COMMIT() asm volatile("cp.async.commit_group;" ::: "memory")
#define CPA_WAIT()   asm volatile("cp.async.wait_group 0;" ::: "memory")

// ---------------- precomputed operand images (bf16 hi/lo, stride-136) ----------------
__device__ __align__(16) __nv_bfloat16 g_Mt_hi[128 * 136];
__device__ __align__(16) __nv_bfloat16 g_Mt_lo[128 * 136];
__device__ __align__(16) __nv_bfloat16 g_Wv_hi[128 * 136];
__device__ __align__(16) __nv_bfloat16 g_Wv_lo[128 * 136];

__global__ void prep_kernel(const float* __restrict__ Wq, const float* __restrict__ Wk,
                            const float* __restrict__ Wv) {
    int n = blockIdx.x, k = threadIdx.x;
    float acc = 0.f;
#pragma unroll 8
    for (int l = 0; l < FD; ++l)
        acc += Wq[l * FD + k] * Wk[l * FD + n];
    acc *= 0.08838834764831845f;  // 1/sqrt(128)
    int idx = n * 136 + k;
    __nv_bfloat16 h = __float2bfloat16(acc);
    g_Mt_hi[idx] = h;
    g_Mt_lo[idx] = __float2bfloat16(acc - __bfloat162float(h));
    float wv = Wv[n * FD + k];
    h = __float2bfloat16(wv);
    g_Wv_hi[idx] = h;
    g_Wv_lo[idx] = __float2bfloat16(wv - __bfloat162float(h));
}

// load a 128x128 fp32 tile (row r = it*32+b), split, store hi/lo stride-136
__device__ __forceinline__ void load_split(const float* __restrict__ base, uint32_t i0,
                                           char* sm, uint32_t dHi, uint32_t dLo, int t) {
    int r = t >> 1;
    int h4 = (t & 1) * 4;
    const float* row = base + ((size_t)(r & 31) * S_LEN + (i0 + (r >> 5))) * FD;
#pragma unroll
    for (int u = 0; u < 16; ++u) {
        int col = 8 * u + h4;
        float4 x = *(const float4*)(row + col);
        uint32_t h0, l0, h1, l1;
        split2(x.x, x.y, h0, l0);
        split2(x.z, x.w, h1, l1);
        sts_pair(sm, dHi, r, col, h0);
        sts_pair(sm, dHi, r, col + 2, h1);
        sts_pair(sm, dLo, r, col, l0);
        sts_pair(sm, dLo, r, col + 2, l1);
    }
}

// full 128x128x128 bf16x3 GEMM, warp tile 32m x 64n, fused 3-pass per k-step:
// each k-step loads aH,aL,bH,bL once and issues hi*hi + hi*lo + lo*hi MMAs.
__device__ __forceinline__ void gemm_full(uint32_t sbase, float acc[2][8][4],
                                          int mBase, int nBase,
                                          uint32_t aLane, uint32_t bLane,
                                          uint32_t aH, uint32_t aL,
                                          uint32_t bH, uint32_t bL) {
    const uint32_t aOffH = sbase + aH + aLane + mBase * STB;
    const uint32_t aOffL = sbase + aL + aLane + mBase * STB;
    const uint32_t bOffH = sbase + bH + bLane + nBase * STB;
    const uint32_t bOffL = sbase + bL + bLane + nBase * STB;
#pragma unroll
    for (int ks = 0; ks < 8; ++ks) {
        uint32_t kb = ks * 32;
        uint32_t ah[2][4], al[2][4];
        ldsm4(ah[0], aOffH + kb);
        ldsm4(ah[1], aOffH + 16 * STB + kb);
        ldsm4(al[0], aOffL + kb);
        ldsm4(al[1], aOffL + 16 * STB + kb);
#pragma unroll
        for (int p = 0; p < 4; ++p) {
            uint32_t bh[4], bl[4];
            ldsm4(bh, bOffH + p * 16 * STB + kb);
            ldsm4(bl, bOffL + p * 16 * STB + kb);
            // hi*hi
            mma16816(acc[0][2 * p],     ah[0], bh[0], bh[1]);
            mma16816(acc[0][2 * p + 1], ah[0], bh[2], bh[3]);
            mma16816(acc[1][2 * p],     ah[1], bh[0], bh[1]);
            mma16816(acc[1][2 * p + 1], ah[1], bh[2], bh[3]);
            // hi*lo
            mma16816(acc[0][2 * p],     ah[0], bl[0], bl[1]);
            mma16816(acc[0][2 * p + 1], ah[0], bl[2], bl[3]);
            mma16816(acc[1][2 * p],     ah[1], bl[0], bl[1]);
            mma16816(acc[1][2 * p + 1], ah[1], bl[2], bl[3]);
            // lo*hi
            mma16816(acc[0][2 * p],     al[0], bh[0], bh[1]);
            mma16816(acc[0][2 * p + 1], al[0], bh[2], bh[3]);
            mma16816(acc[1][2 * p],     al[1], bh[0], bh[1]);
            mma16816(acc[1][2 * p + 1], al[1], bh[2], bh[3]);
        }
    }
}

__global__ __launch_bounds__(NT, 1)
void fused_attn_mma(const float* __restrict__ Q, const float* __restrict__ K,
                    const float* __restrict__ V, float* __restrict__ Out) {
    extern __shared__ char sm[];
    const uint32_t sbase = smem_u32(sm);
    const int t = threadIdx.x, lane = t & 31, w = t >> 5;
    const int g = lane >> 2, tg = lane & 3;
    const uint32_t i0 = blockIdx.x * TI;

    // LDSM per-lane address components
    const uint32_t aLane = (uint32_t)(lane & 15) * STB + (uint32_t)(lane >> 4) * 16;
    const uint32_t bLane = (uint32_t)((lane & 7) + ((lane & 16) >> 1)) * STB + (uint32_t)(lane & 8) * 2;
    const uint32_t tLane = (uint32_t)((lane & 7) + (lane & 8)) * STB + (uint32_t)(lane >> 4) * 16;

    // ---- P0: Mt -> B1 (cp.async), Q -> A, K -> B2 ----
    {
        const char* mh = (const char*)g_Mt_hi;
        const char* ml = (const char*)g_Mt_lo;
#pragma unroll
        for (int u = 0; u < 9; ++u) {
            int i = u * NT + t;
            if (i < 2176) {
                cpa16(sbase + B1_HI + i * 16, mh + i * 16);
                cpa16(sbase + B1_LO + i * 16, ml + i * 16);
            }
        }
        CPA_COMMIT();
    }
    load_split(Q, i0, sm, A_HI, A_LO, t);
    load_split(K, i0, sm, B2_HI, B2_LO, t);
    CPA_WAIT();
    __syncthreads();

    // ---- G1: QM = Q @ Mt^T ----
    const int mB = (w >> 1) * 32, nB = (w & 1) * 64;
    float acc[2][8][4];
#pragma unroll
    for (int mt = 0; mt < 2; ++mt)
#pragma unroll
        for (int nt = 0; nt < 8; ++nt)
#pragma unroll
            for (int j = 0; j < 4; ++j) acc[mt][nt][j] = 0.f;
    gemm_full(sbase, acc, mB, nB, aLane, bLane, A_HI, A_LO, B1_HI, B1_LO);
    __syncthreads();

    // ---- P1: QM frags -> A (hi/lo); V (natural layout) -> B1 ----
#pragma unroll
    for (int mt = 0; mt < 2; ++mt)
#pragma unroll
        for (int nt = 0; nt < 8; ++nt) {
            int r = mB + mt * 16 + g, c = nB + nt * 8 + tg * 2;
            uint32_t h, l;
            split2(acc[mt][nt][0], acc[mt][nt][1], h, l);
            sts_pair(sm, A_HI, r, c, h);
            sts_pair(sm, A_LO, r, c, l);
            split2(acc[mt][nt][2], acc[mt][nt][3], h, l);
            sts_pair(sm, A_HI, r + 8, c, h);
            sts_pair(sm, A_LO, r + 8, c, l);
        }
    load_split(V, i0, sm, B1_HI, B1_LO, t);
    __syncthreads();

    // ---- G2: diagonal scores (warp strip: 16 rows x 32 cols), fused 3-pass ----
    const int it = w >> 1;
    const int mB2 = it * 32 + (w & 1) * 16;
    const int nB2 = it * 32;
    float sc[4][4];
#pragma unroll
    for (int nt = 0; nt < 4; ++nt)
#pragma unroll
        for (int j = 0; j < 4; ++j) sc[nt][j] = 0.f;
    {
        const uint32_t aOffH = sbase + A_HI + aLane + mB2 * STB;
        const uint32_t aOffL = sbase + A_LO + aLane + mB2 * STB;
        const uint32_t bOffH = sbase + B2_HI + bLane + nB2 * STB;
        const uint32_t bOffL = sbase + B2_LO + bLane + nB2 * STB;
#pragma unroll
        for (int ks = 0; ks < 8; ++ks) {
            uint32_t kb = ks * 32;
            uint32_t ah[4], al[4];
            ldsm4(ah, aOffH + kb);
            ldsm4(al, aOffL + kb);
            uint32_t bh0[4], bh1[4], bl0[4], bl1[4];
            ldsm4(bh0, bOffH + kb);
            ldsm4(bh1, bOffH + 16 * STB + kb);
            ldsm4(bl0, bOffL + kb);
            ldsm4(bl1, bOffL + 16 * STB + kb);
            // hi*hi
            mma16816(sc[0], ah, bh0[0], bh0[1]);
            mma16816(sc[1], ah, bh0[2], bh0[3]);
            mma16816(sc[2], ah, bh1[0], bh1[1]);
            mma16816(sc[3], ah, bh1[2], bh1[3]);
            // hi*lo
            mma16816(sc[0], ah, bl0[0], bl0[1]);
            mma16816(sc[1], ah, bl0[2], bl0[3]);
            mma16816(sc[2], ah, bl1[0], bl1[1]);
            mma16816(sc[3], ah, bl1[2], bl1[3]);
            // lo*hi
            mma16816(sc[0], al, bh0[0], bh0[1]);
            mma16816(sc[1], al, bh0[2], bh0[3]);
            mma16816(sc[2], al, bh1[0], bh1[1]);
            mma16816(sc[3], al, bh1[2], bh1[3]);
        }
    }

    // ---- softmax over 32 cols (rows g and g+8 of this warp strip) ----
    {
        float mx0 = -1e30f, mx1 = -1e30f;
#pragma unroll
        for (int nt = 0; nt < 4; ++nt) {
            mx0 = fmaxf(mx0, fmaxf(sc[nt][0], sc[nt][1]));
            mx1 = fmaxf(mx1, fmaxf(sc[nt][2], sc[nt][3]));
        }
        mx0 = fmaxf(mx0, __shfl_xor_sync(0xffffffffu, mx0, 1));
        mx0 = fmaxf(mx0, __shfl_xor_sync(0xffffffffu, mx0, 2));
        mx1 = fmaxf(mx1, __shfl_xor_sync(0xffffffffu, mx1, 1));
        mx1 = fmaxf(mx1, __shfl_xor_sync(0xffffffffu, mx1, 2));
        float s0 = 0.f, s1 = 0.f;
#pragma unroll
        for (int nt = 0; nt < 4; ++nt) {
            sc[nt][0] = __expf(sc[nt][0] - mx0);
            sc[nt][1] = __expf(sc[nt][1] - mx0);
            sc[nt][2] = __expf(sc[nt][2] - mx1);
            sc[nt][3] = __expf(sc[nt][3] - mx1);
            s0 += sc[nt][0] + sc[nt][1];
            s1 += sc[nt][2] + sc[nt][3];
        }
        s0 += __shfl_xor_sync(0xffffffffu, s0, 1);
        s0 += __shfl_xor_sync(0xffffffffu, s0, 2);
        s1 += __shfl_xor_sync(0xffffffffu, s1, 1);
        s1 += __shfl_xor_sync(0xffffffffu, s1, 2);
        float i0v = 1.f / s0, i1v = 1.f / s1;
#pragma unroll
        for (int nt = 0; nt < 4; ++nt) {
            sc[nt][0] *= i0v; sc[nt][1] *= i0v;
            sc[nt][2] *= i1v; sc[nt][3] *= i1v;
        }
    }
    // attn A-fragments (hi/lo) directly from D-fragments (layouts coincide)
    uint32_t a3H[2][4], a3L[2][4];
#pragma unroll
    for (int ks = 0; ks < 2; ++ks) {
        int n0 = ks * 2, n1 = ks * 2 + 1;
        split2(sc[n0][0], sc[n0][1], a3H[ks][0], a3L[ks][0]);
        split2(sc[n0][2], sc[n0][3], a3H[ks][1], a3L[ks][1]);
        split2(sc[n1][0], sc[n1][1], a3H[ks][2], a3L[ks][2]);
        split2(sc[n1][2], sc[n1][3], a3H[ks][3], a3L[ks][3]);
    }
    __syncthreads();   // everyone done reading A (QM) and B2 (K)

    // ---- Wv -> B2 via cp.async, overlapped with G3 ----
    {
        const char* wh = (const char*)g_Wv_hi;
        const char* wl = (const char*)g_Wv_lo;
#pragma unroll
        for (int u = 0; u < 9; ++u) {
            int i = u * NT + t;
            if (i < 2176) {
                cpa16(sbase + B2_HI + i * 16, wh + i * 16);
                cpa16(sbase + B2_LO + i * 16, wl + i * 16);
            }
        }
        CPA_COMMIT();
    }

    // ---- G3: raw = attn(block-diag) @ V, fused 3-pass (B via ldmatrix.trans) ----
    float acc3[16][4];
#pragma unroll
    for (int nt = 0; nt < 16; ++nt)
#pragma unroll
        for (int j = 0; j < 4; ++j) acc3[nt][j] = 0.f;
    {
        const uint32_t bOffH = sbase + B1_HI + tLane + (uint32_t)(it * 32) * STB;
        const uint32_t bOffL = sbase + B1_LO + tLane + (uint32_t)(it * 32) * STB;
#pragma unroll
        for (int ks = 0; ks < 2; ++ks) {
            uint32_t krow = (uint32_t)(ks * 16) * STB;
#pragma unroll
            for (int p = 0; p < 8; ++p) {
                uint32_t bh[4], bl[4];
                ldsm4t(bh, bOffH + krow + p * 32);
                ldsm4t(bl, bOffL + krow + p * 32);
                // hi*hi
                mma16816(acc3[2 * p],     a3H[ks], bh[0], bh[1]);
                mma16816(acc3[2 * p + 1], a3H[ks], bh[2], bh[3]);
                // hi*lo
                mma16816(acc3[2 * p],     a3H[ks], bl[0], bl[1]);
                mma16816(acc3[2 * p + 1], a3H[ks], bl[2], bl[3]);
                // lo*hi
                mma16816(acc3[2 * p],     a3L[ks], bh[0], bh[1]);
                mma16816(acc3[2 * p + 1], a3L[ks], bh[2], bh[3]);
            }
        }
    }

    // ---- raw frags -> A (hi/lo) ----
    {
        int r0 = it * 32 + (w & 1) * 16 + g;
#pragma unroll
        for (int nt = 0; nt < 16; ++nt) {
            int c = nt * 8 + tg * 2;
            uint32_t h, l;
            split2(acc3[nt][0], acc3[nt][1], h, l);
            sts_pair(sm, A_HI, r0, c, h);
            sts_pair(sm, A_LO, r0, c, l);
            split2(acc3[nt][2], acc3[nt][3], h, l);
            sts_pair(sm, A_HI, r0 + 8, c, h);
            sts_pair(sm, A_LO, r0 + 8, c, l);
        }
    }
    CPA_WAIT();
    __syncthreads();

    // ---- G4: Out = raw @ Wv^T ----
    float acc4[2][8][4];
#pragma unroll
    for (int mt = 0; mt < 2; ++mt)
#pragma unroll
        for (int nt = 0; nt < 8; ++nt)
#pragma unroll
            for (int j = 0; j < 4; ++j) acc4[mt][nt][j] = 0.f;
    gemm_full(sbase, acc4, mB, nB, aLane, bLane, A_HI, A_LO, B2_HI, B2_LO);

    // ---- store ----
#pragma unroll
    for (int mt = 0; mt < 2; ++mt) {
        int r = mB + mt * 16 + g;
#pragma unroll
        for (int nt = 0; nt < 8; ++nt) {
            int c = nB + nt * 8 + tg * 2;
            {
                int b = r & 31, itt = r >> 5;
                float2 v = {acc4[mt][nt][0], acc4[mt][nt][1]};
                *(float2*)(Out + ((size_t)b * S_LEN + (i0 + itt)) * FD + c) = v;
            }
            {
                int r8 = r + 8;
                int b = r8 & 31, itt = r8 >> 5;
                float2 v = {acc4[mt][nt][2], acc4[mt][nt][3]};
                *(float2*)(Out + ((size_t)b * S_LEN + (i0 + itt)) * FD + c) = v;
            }
        }
    }
}

extern "C" void kernel_launch(void* const* d_in, const int* in_sizes, int n_in,
                              void* d_out, int out_size) {
    const float* q  = (const float*)d_in[0];
    const float* k  = (const float*)d_in[1];
    const float* v  = (const float*)d_in[2];
    const float* Wq = (const float*)d_in[3];
    const float* Wk = (const float*)d_in[4];
    const float* Wv = (const float*)d_in[5];
    float* out = (float*)d_out;

    prep_kernel<<<FD, FD>>>(Wq, Wk, Wv);

    cudaFuncSetAttribute(fused_attn_mma,
                         cudaFuncAttributeMaxDynamicSharedMemorySize, SMEM_BYTES);
    fused_attn_mma<<<S_LEN / TI, NT, SMEM_BYTES>>>(q, k, v, out);
}